// round 1
// baseline (speedup 1.0000x reference)
#include <cuda_runtime.h>

#define Bn 64
#define Nn 512
#define Kk 32
#define Dd 64
#define BN_TOTAL (Bn*Nn)   // 32768
#define EPSf 1e-5f
#define NEG_SLOPE 0.2f
#define NEG_INFf -1e9f

// ---- scratch (static device globals; no allocation) ----
__device__ float g_nrm[Nn];
__device__ float g_edot_i[Nn];
__device__ float g_edot_j[Nn];
__device__ int   g_topk[Nn * Kk];
__device__ float g_xl[(size_t)BN_TOTAL * Dd];   // 8 MB
__device__ float g_ci[BN_TOTAL];
__device__ float g_cj[BN_TOTAL];

// ---------------------------------------------------------------
// Kernel 1: per-embedding-row norm and dot products with att_em_{i,j}
// ---------------------------------------------------------------
__global__ void k_norms(const float* __restrict__ emb,
                        const float* __restrict__ att_em_i,
                        const float* __restrict__ att_em_j) {
    int n = blockIdx.x * blockDim.x + threadIdx.x;
    if (n >= Nn) return;
    const float* row = emb + n * Dd;
    float s2 = 0.f, di = 0.f, dj = 0.f;
#pragma unroll 8
    for (int d = 0; d < Dd; d++) {
        float e = row[d];
        s2 += e * e;
        di += e * att_em_i[d];
        dj += e * att_em_j[d];
    }
    g_nrm[n]    = sqrtf(s2);
    g_edot_i[n] = di;
    g_edot_j[n] = dj;
}

// ---------------------------------------------------------------
// Kernel 2: cosine similarity row + top-K selection (one block/row)
// tie-break: smaller index wins (matches jax.lax.top_k)
// ---------------------------------------------------------------
__global__ void k_topk(const float* __restrict__ emb) {
    __shared__ float s_cos[Nn];
    __shared__ float s_row[Dd];
    __shared__ unsigned long long s_red[256];

    const int i = blockIdx.x;
    const int t = threadIdx.x;

    if (t < Dd) s_row[t] = emb[i * Dd + t];
    __syncthreads();

    const float inv_ni = 1.0f / g_nrm[i];
    for (int j = t; j < Nn; j += 256) {
        const float4* rj = (const float4*)(emb + j * Dd);
        float dot = 0.f;
#pragma unroll
        for (int q = 0; q < Dd / 4; q++) {
            float4 v = rj[q];
            dot += v.x * s_row[4 * q]     + v.y * s_row[4 * q + 1]
                 + v.z * s_row[4 * q + 2] + v.w * s_row[4 * q + 3];
        }
        s_cos[j] = dot * inv_ni / g_nrm[j];
    }
    __syncthreads();

    for (int k = 0; k < Kk; k++) {
        // local best over this thread's strided entries
        unsigned long long best = 0ull;
        for (int j = t; j < Nn; j += 256) {
            unsigned int bits = __float_as_uint(s_cos[j]);
            bits = (bits & 0x80000000u) ? ~bits : (bits | 0x80000000u); // order-preserving
            unsigned long long key =
                ((unsigned long long)bits << 32) | (unsigned int)(Nn - 1 - j);
            if (key > best) best = key;
        }
        s_red[t] = best;
        __syncthreads();
#pragma unroll
        for (int s = 128; s > 0; s >>= 1) {
            if (t < s && s_red[t + s] > s_red[t]) s_red[t] = s_red[t + s];
            __syncthreads();
        }
        int jbest = Nn - 1 - (int)(s_red[0] & 0xFFFFFFFFu);
        if (t == 0) {
            g_topk[i * Kk + k] = jbest;
            s_cos[jbest] = -2.0f;   // remove from further rounds
        }
        __syncthreads();
    }
}

// ---------------------------------------------------------------
// Kernel 3: xl = x @ W^T  and per-node attention scalars ci, cj
// 256 threads = 8 nodes x 32 lanes; lane t handles channels t and t+32
// ---------------------------------------------------------------
__global__ void k_xl(const float* __restrict__ x,
                     const float* __restrict__ W,
                     const float* __restrict__ att_i,
                     const float* __restrict__ att_j) {
    __shared__ float s_W[Dd][Dd + 1];   // s_W[k][d] = W[d][k], padded -> conflict-free
    __shared__ float s_x[8][Dd];

    const int tid = threadIdx.x;
    const int w = tid >> 5, t = tid & 31;
    const int node = blockIdx.x * 8 + w;

    // cooperative transposed load of W (coalesced gmem read, conflict-free smem write)
    for (int idx = tid; idx < Dd * Dd; idx += 256) {
        int d = idx >> 6, k = idx & 63;
        s_W[k][d] = W[idx];
    }
    // load this node's input row (coalesced float2)
    {
        const float2* xr = (const float2*)(x + (size_t)node * Dd);
        float2 v = xr[t];
        s_x[w][2 * t]     = v.x;
        s_x[w][2 * t + 1] = v.y;
    }
    __syncthreads();

    const int d0 = t, d1 = t + 32;
    float acc0 = 0.f, acc1 = 0.f;
#pragma unroll
    for (int k = 0; k < Dd; k++) {
        float xk = s_x[w][k];                 // broadcast
        acc0 += xk * s_W[k][d0];              // banks (k+t)%32 -> conflict-free
        acc1 += xk * s_W[k][d1];
    }

    float* xlrow = g_xl + (size_t)node * Dd;
    xlrow[d0] = acc0;
    xlrow[d1] = acc1;

    // ci, cj via warp reduction
    float pi = acc0 * att_i[d0] + acc1 * att_i[d1];
    float pj = acc0 * att_j[d0] + acc1 * att_j[d1];
#pragma unroll
    for (int o = 16; o > 0; o >>= 1) {
        pi += __shfl_xor_sync(0xFFFFFFFFu, pi, o);
        pj += __shfl_xor_sync(0xFFFFFFFFu, pj, o);
    }
    if (t == 0) {
        int n = node % Nn;
        g_ci[node] = pi + g_edot_i[n];
        g_cj[node] = pj + g_edot_j[n];
    }
}

// ---------------------------------------------------------------
// Kernel 4: attention softmax (33 edges/node) + aggregation + epilogue
// 256 threads = 8 nodes x 32 lanes
// ---------------------------------------------------------------
__global__ void k_attn(const float* __restrict__ emb,
                       const float* __restrict__ gnn_bias,
                       const float* __restrict__ bn1_gamma, const float* __restrict__ bn1_beta,
                       const float* __restrict__ bn1_mean,  const float* __restrict__ bn1_var,
                       const float* __restrict__ bno_gamma, const float* __restrict__ bno_beta,
                       const float* __restrict__ bno_mean,  const float* __restrict__ bno_var,
                       const float* __restrict__ out_W,     const float* __restrict__ out_b,
                       float* __restrict__ out) {
    __shared__ float s_wgt[8][33];
    __shared__ int   s_src[8][33];

    const int tid = threadIdx.x;
    const int w = tid >> 5, t = tid & 31;
    const int node = blockIdx.x * 8 + w;
    const int b = node / Nn;
    const int i = node - b * Nn;
    const int base = b * Nn;

    const float ci = g_ci[node];

    // edge t (top-k neighbor)
    const int srcj = g_topk[i * Kk + t];
    const bool valid = (srcj != i);
    float lg = ci + g_cj[base + srcj];
    lg = (lg >= 0.f) ? lg : NEG_SLOPE * lg;     // leaky relu
    if (!valid) lg = NEG_INFf;                  // mask AFTER leaky relu (matches ref)

    // self-loop edge (always valid)
    float lgs = ci + g_cj[node];
    lgs = (lgs >= 0.f) ? lgs : NEG_SLOPE * lgs;

    // stable softmax over 33 logits
    float m = lg;
#pragma unroll
    for (int o = 16; o > 0; o >>= 1) m = fmaxf(m, __shfl_xor_sync(0xFFFFFFFFu, m, o));
    m = fmaxf(m, lgs);

    float ex  = valid ? __expf(lg - m) : 0.0f;
    float exs = __expf(lgs - m);
    float sum = ex;
#pragma unroll
    for (int o = 16; o > 0; o >>= 1) sum += __shfl_xor_sync(0xFFFFFFFFu, sum, o);
    sum += exs;
    const float inv = 1.0f / sum;

    s_wgt[w][t] = ex * inv;
    s_src[w][t] = base + srcj;
    if (t == 0) {
        s_wgt[w][32] = exs * inv;
        s_src[w][32] = node;
    }
    __syncwarp();

    // weighted aggregation of xl rows (coalesced 128B loads per lane-group)
    float acc0 = 0.f, acc1 = 0.f;
#pragma unroll
    for (int e = 0; e < 33; e++) {
        float wg = s_wgt[w][e];
        const float* row = g_xl + (size_t)s_src[w][e] * Dd;
        acc0 += wg * row[t];
        acc1 += wg * row[t + 32];
    }

    // epilogue: +bias, BN1, relu, *emb, BNo, relu, Linear(D,1)
    const int c0 = t, c1 = t + 32;
    float h0 = acc0 + gnn_bias[c0];
    float h1 = acc1 + gnn_bias[c1];
    h0 = (h0 - bn1_mean[c0]) * rsqrtf(bn1_var[c0] + EPSf) * bn1_gamma[c0] + bn1_beta[c0];
    h1 = (h1 - bn1_mean[c1]) * rsqrtf(bn1_var[c1] + EPSf) * bn1_gamma[c1] + bn1_beta[c1];
    h0 = fmaxf(h0, 0.f) * emb[i * Dd + c0];
    h1 = fmaxf(h1, 0.f) * emb[i * Dd + c1];
    h0 = (h0 - bno_mean[c0]) * rsqrtf(bno_var[c0] + EPSf) * bno_gamma[c0] + bno_beta[c0];
    h1 = (h1 - bno_mean[c1]) * rsqrtf(bno_var[c1] + EPSf) * bno_gamma[c1] + bno_beta[c1];
    h0 = fmaxf(h0, 0.f);
    h1 = fmaxf(h1, 0.f);

    float p = h0 * out_W[c0] + h1 * out_W[c1];
#pragma unroll
    for (int o = 16; o > 0; o >>= 1) p += __shfl_xor_sync(0xFFFFFFFFu, p, o);
    if (t == 0) out[node] = p + out_b[0];
}

// ---------------------------------------------------------------
extern "C" void kernel_launch(void* const* d_in, const int* in_sizes, int n_in,
                              void* d_out, int out_size) {
    (void)in_sizes; (void)n_in; (void)out_size;
    const float* data      = (const float*)d_in[0];
    /* d_in[1] = org_edge_index (int32) — unused by the model */
    const float* emb       = (const float*)d_in[2];
    const float* lin_W     = (const float*)d_in[3];
    const float* att_i     = (const float*)d_in[4];
    const float* att_j     = (const float*)d_in[5];
    const float* att_em_i  = (const float*)d_in[6];
    const float* att_em_j  = (const float*)d_in[7];
    const float* gnn_bias  = (const float*)d_in[8];
    const float* bn1_gamma = (const float*)d_in[9];
    const float* bn1_beta  = (const float*)d_in[10];
    const float* bn1_mean  = (const float*)d_in[11];
    const float* bn1_var   = (const float*)d_in[12];
    const float* bno_gamma = (const float*)d_in[13];
    const float* bno_beta  = (const float*)d_in[14];
    const float* bno_mean  = (const float*)d_in[15];
    const float* bno_var   = (const float*)d_in[16];
    const float* out_W     = (const float*)d_in[17];
    const float* out_b     = (const float*)d_in[18];
    float* out = (float*)d_out;

    k_norms<<<(Nn + 255) / 256, 256>>>(emb, att_em_i, att_em_j);
    k_topk<<<Nn, 256>>>(emb);
    k_xl<<<BN_TOTAL / 8, 256>>>(data, lin_W, att_i, att_j);
    k_attn<<<BN_TOTAL / 8, 256>>>(emb, gnn_bias,
                                  bn1_gamma, bn1_beta, bn1_mean, bn1_var,
                                  bno_gamma, bno_beta, bno_mean, bno_var,
                                  out_W, out_b, out);
}

// round 2
// speedup vs baseline: 1.6022x; 1.6022x over previous
#include <cuda_runtime.h>

#define Bn 64
#define Nn 512
#define Kk 32
#define Dd 64
#define BN_TOTAL (Bn*Nn)   // 32768
#define EPSf 1e-5f
#define NEG_SLOPE 0.2f
#define NEG_INFf -1e9f

// ---- scratch (static device globals; no allocation) ----
__device__ float g_nrm[Nn];
__device__ float g_edot_i[Nn];
__device__ float g_edot_j[Nn];
__device__ int   g_topk[Nn * Kk];
__device__ float g_xl[(size_t)BN_TOTAL * Dd];   // 8 MB
__device__ float g_ci[BN_TOTAL];
__device__ float g_cj[BN_TOTAL];

// ---------------------------------------------------------------
// Kernel 1: per-embedding-row norm and dot products with att_em_{i,j}
// ---------------------------------------------------------------
__global__ void k_norms(const float* __restrict__ emb,
                        const float* __restrict__ att_em_i,
                        const float* __restrict__ att_em_j) {
    int n = blockIdx.x * blockDim.x + threadIdx.x;
    if (n >= Nn) return;
    const float* row = emb + n * Dd;
    float s2 = 0.f, di = 0.f, dj = 0.f;
#pragma unroll 8
    for (int d = 0; d < Dd; d++) {
        float e = row[d];
        s2 += e * e;
        di += e * att_em_i[d];
        dj += e * att_em_j[d];
    }
    g_nrm[n]    = sqrtf(s2);
    g_edot_i[n] = di;
    g_edot_j[n] = dj;
}

// ---------------------------------------------------------------
// Kernel 2: warp-per-row cosine top-K. Keys live in registers
// (16 uint64 per lane), 32 argmax rounds via warp shuffles only.
// Tie-break: smaller index wins (matches jax.lax.top_k).
// ---------------------------------------------------------------
__global__ void __launch_bounds__(128)
k_topk(const float* __restrict__ emb) {
    const int w = threadIdx.x >> 5;           // warp in block
    const int t = threadIdx.x & 31;           // lane
    const int i = blockIdx.x * 4 + w;         // row handled by this warp

    // row i into registers (all lanes same address -> broadcast loads)
    float4 ri[16];
    const float4* rowi = (const float4*)(emb + i * Dd);
#pragma unroll
    for (int q = 0; q < 16; q++) ri[q] = rowi[q];

    const float inv_i = 1.0f / g_nrm[i];

    // cos for j = t + 32*m, m = 0..15; build order-preserving keys
    unsigned long long key[16];
#pragma unroll
    for (int m = 0; m < 16; m++) {
        const int j = t + 32 * m;
        const float4* rj = (const float4*)(emb + j * Dd);
        float d0 = 0.f, d1 = 0.f, d2 = 0.f, d3 = 0.f;
#pragma unroll
        for (int q = 0; q < 16; q += 4) {
            float4 a0 = rj[q], a1 = rj[q + 1], a2 = rj[q + 2], a3 = rj[q + 3];
            d0 += a0.x * ri[q].x     + a0.y * ri[q].y     + a0.z * ri[q].z     + a0.w * ri[q].w;
            d1 += a1.x * ri[q + 1].x + a1.y * ri[q + 1].y + a1.z * ri[q + 1].z + a1.w * ri[q + 1].w;
            d2 += a2.x * ri[q + 2].x + a2.y * ri[q + 2].y + a2.z * ri[q + 2].z + a2.w * ri[q + 2].w;
            d3 += a3.x * ri[q + 3].x + a3.y * ri[q + 3].y + a3.z * ri[q + 3].z + a3.w * ri[q + 3].w;
        }
        float cosv = __fdividef((d0 + d1) + (d2 + d3) * 1.0f, 1.0f) * inv_i;
        cosv = __fdividef(((d0 + d1) + (d2 + d3)) * inv_i, g_nrm[j]);
        unsigned int bits = __float_as_uint(cosv);
        bits = (bits & 0x80000000u) ? ~bits : (bits | 0x80000000u);
        key[m] = ((unsigned long long)bits << 32) | (unsigned int)(Nn - 1 - j);
    }

    // 32 rounds of warp argmax
    for (int k = 0; k < Kk; k++) {
        unsigned long long best = 0ull;
#pragma unroll
        for (int m = 0; m < 16; m++) best = (key[m] > best) ? key[m] : best;
#pragma unroll
        for (int o = 16; o > 0; o >>= 1) {
            unsigned long long v = __shfl_xor_sync(0xFFFFFFFFu, best, o);
            best = (v > best) ? v : best;
        }
        // remove winner from its owner lane (index encoded -> unique)
#pragma unroll
        for (int m = 0; m < 16; m++) if (key[m] == best) key[m] = 0ull;
        if (t == 0) g_topk[i * Kk + k] = Nn - 1 - (int)(best & 0xFFFFFFFFu);
    }
}

// ---------------------------------------------------------------
// Kernel 3: xl = x @ W^T and per-node scalars ci, cj.
// 256 threads = 8 warps; each warp register-blocks 8 nodes.
// ---------------------------------------------------------------
__global__ void __launch_bounds__(256)
k_xl(const float* __restrict__ x,
     const float* __restrict__ W,
     const float* __restrict__ att_i,
     const float* __restrict__ att_j) {
    __shared__ float s_W[Dd][Dd + 1];   // s_W[k][d] = W[d][k] (transposed, padded)
    __shared__ float s_x[64][Dd];       // 64 nodes per block

    const int tid = threadIdx.x;
    const int w = tid >> 5, t = tid & 31;
    const int node_blk = blockIdx.x * 64;

    // transposed load of W
    for (int idx = tid; idx < Dd * Dd; idx += 256) {
        int d = idx >> 6, k = idx & 63;
        s_W[k][d] = W[idx];
    }
    // 64 input rows, coalesced float4
    {
        const float4* xs = (const float4*)(x + (size_t)node_blk * Dd);
        float4* xd = (float4*)&s_x[0][0];
#pragma unroll
        for (int q = 0; q < 4; q++) xd[tid + 256 * q] = xs[tid + 256 * q];
    }
    __syncthreads();

    const float ai0 = att_i[t], ai1 = att_i[t + 32];
    const float aj0 = att_j[t], aj1 = att_j[t + 32];

    float acc0[8], acc1[8];
#pragma unroll
    for (int n = 0; n < 8; n++) { acc0[n] = 0.f; acc1[n] = 0.f; }

    const int nl0 = w * 8;              // this warp's first local node
#pragma unroll
    for (int k = 0; k < Dd; k++) {
        const float w0 = s_W[k][t];     // banks (k+t)%32 -> conflict-free
        const float w1 = s_W[k][t + 32];
#pragma unroll
        for (int n = 0; n < 8; n++) {
            const float xk = s_x[nl0 + n][k];   // broadcast
            acc0[n] += xk * w0;
            acc1[n] += xk * w1;
        }
    }

#pragma unroll
    for (int n = 0; n < 8; n++) {
        const int node = node_blk + nl0 + n;
        float* xlrow = g_xl + (size_t)node * Dd;
        xlrow[t]      = acc0[n];
        xlrow[t + 32] = acc1[n];

        float pi = acc0[n] * ai0 + acc1[n] * ai1;
        float pj = acc0[n] * aj0 + acc1[n] * aj1;
#pragma unroll
        for (int o = 16; o > 0; o >>= 1) {
            pi += __shfl_xor_sync(0xFFFFFFFFu, pi, o);
            pj += __shfl_xor_sync(0xFFFFFFFFu, pj, o);
        }
        if (t == 0) {
            const int nn = node & (Nn - 1);
            g_ci[node] = pi + g_edot_i[nn];
            g_cj[node] = pj + g_edot_j[nn];
        }
    }
}

// ---------------------------------------------------------------
// Kernel 4: smem-tiled attention + epilogue.
// 128 blocks = (batch, half). Each block stages its batch's xl
// (128 KB) in dynamic smem; gather becomes conflict-free LDS.
// ---------------------------------------------------------------
__global__ void __launch_bounds__(512)
k_attn(const float* __restrict__ emb,
       const float* __restrict__ gnn_bias,
       const float* __restrict__ bn1_gamma, const float* __restrict__ bn1_beta,
       const float* __restrict__ bn1_mean,  const float* __restrict__ bn1_var,
       const float* __restrict__ bno_gamma, const float* __restrict__ bno_beta,
       const float* __restrict__ bno_mean,  const float* __restrict__ bno_var,
       const float* __restrict__ out_W,     const float* __restrict__ out_b,
       float* __restrict__ out) {
    extern __shared__ float s_xl[];               // [Nn][Dd] = 128 KB
    __shared__ float  s_cj[Nn];
    __shared__ float2 s_ws[16][33];               // (weight, src) per warp

    const int tid = threadIdx.x;
    const int w = tid >> 5, t = tid & 31;
    const int batch = blockIdx.x >> 1;
    const int half  = blockIdx.x & 1;
    const int base  = batch * Nn;

    // stage xl for this batch + cj
    {
        const float4* src = (const float4*)(g_xl + (size_t)base * Dd);
        float4* dst = (float4*)s_xl;
#pragma unroll
        for (int q = 0; q < (Nn * Dd / 4) / 512; q++)
            dst[tid + 512 * q] = src[tid + 512 * q];
        if (tid < Nn) s_cj[tid] = g_cj[base + tid];
    }
    __syncthreads();

    // per-lane constant epilogue params
    const int c0 = t, c1 = t + 32;
    const float gb0 = gnn_bias[c0], gb1 = gnn_bias[c1];
    const float s10 = rsqrtf(bn1_var[c0] + EPSf) * bn1_gamma[c0];
    const float s11 = rsqrtf(bn1_var[c1] + EPSf) * bn1_gamma[c1];
    const float m10 = bn1_mean[c0], m11 = bn1_mean[c1];
    const float b10 = bn1_beta[c0], b11 = bn1_beta[c1];
    const float so0 = rsqrtf(bno_var[c0] + EPSf) * bno_gamma[c0];
    const float so1 = rsqrtf(bno_var[c1] + EPSf) * bno_gamma[c1];
    const float mo0 = bno_mean[c0], mo1 = bno_mean[c1];
    const float bo0 = bno_beta[c0], bo1 = bno_beta[c1];
    const float ow0 = out_W[c0], ow1 = out_W[c1];
    const float ob  = out_b[0];

#pragma unroll 1
    for (int r = 0; r < 16; r++) {
        const int i = half * 256 + w * 16 + r;    // target node (local)
        const int node = base + i;

        const float ci = g_ci[node];
        const int srcj = g_topk[i * Kk + t];
        const bool valid = (srcj != i);

        float lg = ci + s_cj[srcj];
        lg = (lg >= 0.f) ? lg : NEG_SLOPE * lg;
        if (!valid) lg = NEG_INFf;

        float lgs = ci + s_cj[i];
        lgs = (lgs >= 0.f) ? lgs : NEG_SLOPE * lgs;

        float m = lg;
#pragma unroll
        for (int o = 16; o > 0; o >>= 1) m = fmaxf(m, __shfl_xor_sync(0xFFFFFFFFu, m, o));
        m = fmaxf(m, lgs);

        const float ex  = valid ? __expf(lg - m) : 0.0f;
        const float exs = __expf(lgs - m);
        float sum = ex;
#pragma unroll
        for (int o = 16; o > 0; o >>= 1) sum += __shfl_xor_sync(0xFFFFFFFFu, sum, o);
        sum += exs;
        const float inv = 1.0f / sum;             // warp-uniform

        s_ws[w][t] = make_float2(ex * inv, __int_as_float(srcj));
        __syncwarp();

        // gather: self edge first (weight warp-uniform, no broadcast needed)
        const float wself = exs * inv;
        float acc0 = wself * s_xl[i * Dd + t];
        float acc1 = wself * s_xl[i * Dd + t + 32];
#pragma unroll
        for (int e = 0; e < Kk; e++) {
            const float2 ws = s_ws[w][e];         // 8B broadcast LDS
            const int se = __float_as_int(ws.y);
            const float* row = s_xl + se * Dd;
            acc0 += ws.x * row[t];
            acc1 += ws.x * row[t + 32];
        }
        __syncwarp();

        // epilogue
        float h0 = acc0 + gb0, h1 = acc1 + gb1;
        h0 = (h0 - m10) * s10 + b10;
        h1 = (h1 - m11) * s11 + b11;
        h0 = fmaxf(h0, 0.f) * emb[i * Dd + c0];
        h1 = fmaxf(h1, 0.f) * emb[i * Dd + c1];
        h0 = (h0 - mo0) * so0 + bo0;
        h1 = (h1 - mo1) * so1 + bo1;
        h0 = fmaxf(h0, 0.f);
        h1 = fmaxf(h1, 0.f);

        float p = h0 * ow0 + h1 * ow1;
#pragma unroll
        for (int o = 16; o > 0; o >>= 1) p += __shfl_xor_sync(0xFFFFFFFFu, p, o);
        if (t == 0) out[node] = p + ob;
    }
}

// ---------------------------------------------------------------
extern "C" void kernel_launch(void* const* d_in, const int* in_sizes, int n_in,
                              void* d_out, int out_size) {
    (void)in_sizes; (void)n_in; (void)out_size;
    const float* data      = (const float*)d_in[0];
    /* d_in[1] = org_edge_index — unused by the model */
    const float* emb       = (const float*)d_in[2];
    const float* lin_W     = (const float*)d_in[3];
    const float* att_i     = (const float*)d_in[4];
    const float* att_j     = (const float*)d_in[5];
    const float* att_em_i  = (const float*)d_in[6];
    const float* att_em_j  = (const float*)d_in[7];
    const float* gnn_bias  = (const float*)d_in[8];
    const float* bn1_gamma = (const float*)d_in[9];
    const float* bn1_beta  = (const float*)d_in[10];
    const float* bn1_mean  = (const float*)d_in[11];
    const float* bn1_var   = (const float*)d_in[12];
    const float* bno_gamma = (const float*)d_in[13];
    const float* bno_beta  = (const float*)d_in[14];
    const float* bno_mean  = (const float*)d_in[15];
    const float* bno_var   = (const float*)d_in[16];
    const float* out_W     = (const float*)d_in[17];
    const float* out_b     = (const float*)d_in[18];
    float* out = (float*)d_out;

    static bool attr_done = false;
    if (!attr_done) {
        cudaFuncSetAttribute(k_attn, cudaFuncAttributeMaxDynamicSharedMemorySize,
                             Nn * Dd * (int)sizeof(float));
        attr_done = true;
    }

    k_norms<<<(Nn + 255) / 256, 256>>>(emb, att_em_i, att_em_j);
    k_topk<<<Nn / 4, 128>>>(emb);
    k_xl<<<BN_TOTAL / 64, 256>>>(data, lin_W, att_i, att_j);
    k_attn<<<Bn * 2, 512, Nn * Dd * (int)sizeof(float)>>>(
        emb, gnn_bias,
        bn1_gamma, bn1_beta, bn1_mean, bn1_var,
        bno_gamma, bno_beta, bno_mean, bno_var,
        out_W, out_b, out);
}